// round 4
// baseline (speedup 1.0000x reference)
#include <cuda_runtime.h>
#include <cuda_bf16.h>
#include <cstdint>

// ---------------------------------------------------------------------------
// SpikeLinear: out = x @ W^T + bias, then LIF scan (T=16).
//
// Round 4: bitwise replication of XLA:CPU (aarch64 Grace) Eigen gebp order.
// Eigen multithreaded blocking: kc = min((16384-192)/64, 320) & ~7 = 248.
// Per output: P_j = fmaf-ascending over panel j (restart from 0),
// panels j: [0,248) [248,496) [496,744) [744,992) [992,1024),
// C = ((((P0+P1)+P2)+P3)+P4), then out = C + bias. All fp32.
// ---------------------------------------------------------------------------

#define F_MAX   1024
#define M_MAX   32768
__device__ float g_lin_out[(size_t)M_MAX * F_MAX];   // 128 MiB scratch

#define KC 248               // Eigen panel width hypothesis

#define BM 128
#define BN 64
#define BK 8
#define TM 8
#define TN 4

__global__ __launch_bounds__(256, 2)
void sgemm_bias_eigen_kernel(const float* __restrict__ A,
                             const float* __restrict__ W,
                             const float* __restrict__ bias,
                             float* __restrict__ C,
                             int M, int N, int K) {
    __shared__ float As[BK][BM];   // 4 KB
    __shared__ float Ws[BK][BN];   // 2 KB

    const int tid  = threadIdx.x;          // 0..255
    const int brow = blockIdx.y;
    const int bcol = blockIdx.x;

    const int tcol = tid % (BN / TN);        // 0..15
    const int trow = tid / (BN / TN);        // 0..15

    float cur[TM][TN];   // current panel accumulator (restarted per panel)
    float tot[TM][TN];   // folded panels: ((P0+P1)+P2)+...
    #pragma unroll
    for (int i = 0; i < TM; i++)
        #pragma unroll
        for (int j = 0; j < TN; j++) { cur[i][j] = 0.0f; tot[i][j] = 0.0f; }

    const float* Ab = A + (size_t)brow * BM * K;
    const float* Wb = W + (size_t)bcol * BN * K;

    // loads: A tile 128x8 = 256 float4 (1/thread); W tile 64x8 = 128 float4
    const int a_row = tid / 2;               // 0..127
    const int a_col = (tid % 2) * 4;         // 0 or 4
    const int w_row = tid / 2;
    const int w_col = (tid % 2) * 4;

    for (int k0 = 0; k0 < K; k0 += BK) {
        {
            float4 v = *reinterpret_cast<const float4*>(
                Ab + (size_t)a_row * K + k0 + a_col);
            As[a_col + 0][a_row] = v.x;
            As[a_col + 1][a_row] = v.y;
            As[a_col + 2][a_row] = v.z;
            As[a_col + 3][a_row] = v.w;
        }
        if (w_row < BN) {
            float4 v = *reinterpret_cast<const float4*>(
                Wb + (size_t)w_row * K + k0 + w_col);
            Ws[w_col + 0][w_row] = v.x;
            Ws[w_col + 1][w_row] = v.y;
            Ws[w_col + 2][w_row] = v.z;
            Ws[w_col + 3][w_row] = v.w;
        }
        __syncthreads();

        // strictly ascending k within the panel, single accumulator
        #pragma unroll
        for (int k = 0; k < BK; k++) {
            const float4* As4 = reinterpret_cast<const float4*>(&As[k][0]);
            const float4* Ws4 = reinterpret_cast<const float4*>(&Ws[k][0]);
            float4 a0 = As4[trow * 2 + 0];
            float4 a1 = As4[trow * 2 + 1];
            float4 w  = Ws4[tcol];
            float a_reg[TM] = {a0.x, a0.y, a0.z, a0.w, a1.x, a1.y, a1.z, a1.w};
            float w_reg[TN] = {w.x, w.y, w.z, w.w};
            #pragma unroll
            for (int i = 0; i < TM; i++)
                #pragma unroll
                for (int j = 0; j < TN; j++)
                    cur[i][j] = fmaf(a_reg[i], w_reg[j], cur[i][j]);
        }
        __syncthreads();

        // Eigen panel boundary: fold current panel into output accumulator.
        // Boundaries: k = 248, 496, 744, 992 (all multiples of BK) and K end.
        const int k_end = k0 + BK;
        if ((k_end % KC) == 0 || k_end == K) {
            #pragma unroll
            for (int i = 0; i < TM; i++)
                #pragma unroll
                for (int j = 0; j < TN; j++) {
                    tot[i][j] = tot[i][j] + cur[i][j];  // fl(tot + P_j)
                    cur[i][j] = 0.0f;
                }
        }
    }

    // out = C + bias (single fp32 add, matching XLA's fused bias add)
    const int m0 = brow * BM + trow * TM;
    const int n0 = bcol * BN + tcol * TN;
    #pragma unroll
    for (int i = 0; i < TM; i++) {
        float* crow = C + (size_t)(m0 + i) * N + n0;
        float4 v;
        v.x = tot[i][0] + bias[n0 + 0];
        v.y = tot[i][1] + bias[n0 + 1];
        v.z = tot[i][2] + bias[n0 + 2];
        v.w = tot[i][3] + bias[n0 + 3];
        *reinterpret_cast<float4*>(crow) = v;
    }
}

// ----------------------------- LIF scan ------------------------------------
__global__ void lif_scan_kernel(const float* __restrict__ lin_out,
                                float* __restrict__ spikes,
                                int B, int F) {
    const size_t idx = (size_t)blockIdx.x * blockDim.x + threadIdx.x;
    const size_t BF = (size_t)B * F;
    if (idx >= BF) return;

    float memb = 0.0f;
    size_t off = idx;
    #pragma unroll
    for (int t = 0; t < 16; t++) {
        memb += lin_out[off];
        float s = (memb > 1.0f) ? 1.0f : 0.0f;
        spikes[off] = s;
        memb = (s > 0.0f) ? 0.0f : memb;
        off += BF;
    }
}

// ----------------------------- launch --------------------------------------
extern "C" void kernel_launch(void* const* d_in, const int* in_sizes, int n_in,
                              void* d_out, int out_size) {
    const float* x    = (const float*)d_in[0];  // [T*B, F_IN]
    const float* w    = (const float*)d_in[1];  // [F_OUT, F_IN]
    const float* bias = (const float*)d_in[2];  // [F_OUT]

    const int F_OUT = in_sizes[2];                 // 1024
    const int F_IN  = in_sizes[1] / F_OUT;         // 1024
    const int M     = in_sizes[0] / F_IN;          // 32768
    const int T     = 16;
    const int B     = M / T;

    float* lin_out = nullptr;
    cudaGetSymbolAddress((void**)&lin_out, g_lin_out);

    dim3 grid(F_OUT / BN, M / BM);
    sgemm_bias_eigen_kernel<<<grid, 256>>>(x, w, bias, lin_out, M, F_OUT, F_IN);

    const size_t BF = (size_t)B * F_OUT;
    const int threads = 256;
    const int blocks = (int)((BF + threads - 1) / threads);
    lif_scan_kernel<<<blocks, threads>>>(lin_out, (float*)d_out, B, F_OUT);
}

// round 5
// speedup vs baseline: 1.0876x; 1.0876x over previous
#include <cuda_runtime.h>
#include <cuda_bf16.h>
#include <cstdint>

// ---------------------------------------------------------------------------
// SpikeLinear: out = x @ W^T + bias, then LIF scan (T=16).
//
// Round 5: FFMA2. Same bitwise arithmetic as Round 4 (Eigen kc=248 panel
// replication, rel_err 9.707e-4 PASS), but the inner product uses PTX
// fma.rn.f32x2 (packed 2-wide fp32 FMA) which ptxas never auto-emits.
// Per component it is IEEE-identical to fmaf, so numerics are unchanged;
// throughput doubles (128 fp32 FMA/cyc/SM instead of 64).
//
// Accumulator pairs are packed along m so both a-operands load directly from
// shared as one 64-bit word; w is broadcast-packed {w,w} (4 movs per k).
// Panel folds use add.rn.f32x2 (bitwise = two scalar fp32 adds).
// ---------------------------------------------------------------------------

#define F_MAX   1024
#define M_MAX   32768
__device__ float g_lin_out[(size_t)M_MAX * F_MAX];   // 128 MiB scratch

#define KC 248               // Eigen panel width (validated round 4)

#define BM 128
#define BN 64
#define BK 8
#define TM 8                 // m rows per thread (4 packed pairs)
#define TN 4                 // n cols per thread

#define FMA_F32X2(d, a, b, c) \
    asm("fma.rn.f32x2 %0, %1, %2, %3;" : "=l"(d) : "l"(a), "l"(b), "l"(c))
#define ADD_F32X2_(d, a, b) \
    asm("add.rn.f32x2 %0, %1, %2;" : "=l"(d) : "l"(a), "l"(b))
#define PACK_DUP_F32(d, x) \
    asm("mov.b64 %0, {%1, %2};" : "=l"(d) : "f"(x), "f"(x))
#define UNPACK_F32X2_(lo, hi, p) \
    asm("mov.b64 {%0, %1}, %2;" : "=f"(lo), "=f"(hi) : "l"(p))

__global__ __launch_bounds__(256, 2)
void sgemm_bias_eigen_ffma2_kernel(const float* __restrict__ A,
                                   const float* __restrict__ W,
                                   const float* __restrict__ bias,
                                   float* __restrict__ C,
                                   int M, int N, int K) {
    __shared__ float As[BK][BM];   // 4 KB
    __shared__ float Ws[BK][BN];   // 2 KB

    const int tid  = threadIdx.x;          // 0..255
    const int brow = blockIdx.y;
    const int bcol = blockIdx.x;

    const int tcol = tid % (BN / TN);        // 0..15
    const int trow = tid / (BN / TN);        // 0..15

    // packed accumulators: [m-pair 0..3][n 0..3], each = {m_even, m_odd}
    unsigned long long cur[4][TN];
    unsigned long long tot[4][TN];
    #pragma unroll
    for (int i = 0; i < 4; i++)
        #pragma unroll
        for (int j = 0; j < TN; j++) { cur[i][j] = 0ull; tot[i][j] = 0ull; }

    const float* Ab = A + (size_t)brow * BM * K;
    const float* Wb = W + (size_t)bcol * BN * K;

    // global->shared mapping (same as round 4)
    const int a_row = tid / 2;               // 0..127
    const int a_col = (tid % 2) * 4;         // 0 or 4
    const int w_row = tid / 2;
    const int w_col = (tid % 2) * 4;

    for (int k0 = 0; k0 < K; k0 += BK) {
        {
            float4 v = *reinterpret_cast<const float4*>(
                Ab + (size_t)a_row * K + k0 + a_col);
            As[a_col + 0][a_row] = v.x;
            As[a_col + 1][a_row] = v.y;
            As[a_col + 2][a_row] = v.z;
            As[a_col + 3][a_row] = v.w;
        }
        if (w_row < BN) {
            float4 v = *reinterpret_cast<const float4*>(
                Wb + (size_t)w_row * K + k0 + w_col);
            Ws[w_col + 0][w_row] = v.x;
            Ws[w_col + 1][w_row] = v.y;
            Ws[w_col + 2][w_row] = v.z;
            Ws[w_col + 3][w_row] = v.w;
        }
        __syncthreads();

        // inner product: strictly ascending k, packed pairs along m.
        #pragma unroll
        for (int k = 0; k < BK; k++) {
            // a pairs: 8 consecutive m-rows -> 4 u64 (two 16B shared loads)
            const ulonglong2* As2 =
                reinterpret_cast<const ulonglong2*>(&As[k][trow * TM]);
            ulonglong2 al = As2[0];   // {m0m1, m2m3}
            ulonglong2 ah = As2[1];   // {m4m5, m6m7}
            unsigned long long ap[4] = {al.x, al.y, ah.x, ah.y};

            const float4* Ws4 = reinterpret_cast<const float4*>(&Ws[k][0]);
            float4 w = Ws4[tcol];
            unsigned long long wp[TN];
            PACK_DUP_F32(wp[0], w.x);
            PACK_DUP_F32(wp[1], w.y);
            PACK_DUP_F32(wp[2], w.z);
            PACK_DUP_F32(wp[3], w.w);

            #pragma unroll
            for (int i = 0; i < 4; i++)
                #pragma unroll
                for (int j = 0; j < TN; j++)
                    FMA_F32X2(cur[i][j], ap[i], wp[j], cur[i][j]);
        }
        __syncthreads();

        // Eigen panel boundary fold (k = 248, 496, 744, 992, 1024)
        const int k_end = k0 + BK;
        if ((k_end % KC) == 0 || k_end == K) {
            #pragma unroll
            for (int i = 0; i < 4; i++)
                #pragma unroll
                for (int j = 0; j < TN; j++) {
                    ADD_F32X2_(tot[i][j], tot[i][j], cur[i][j]);
                    cur[i][j] = 0ull;
                }
        }
    }

    // epilogue: unpack, scalar fp32 bias add (identical to round 4), store
    const int m0 = brow * BM + trow * TM;
    const int n0 = bcol * BN + tcol * TN;
    #pragma unroll
    for (int i = 0; i < 4; i++) {
        float lo[TN], hi[TN];
        #pragma unroll
        for (int j = 0; j < TN; j++)
            UNPACK_F32X2_(lo[j], hi[j], tot[i][j]);

        float* crow0 = C + (size_t)(m0 + 2 * i + 0) * N + n0;
        float* crow1 = C + (size_t)(m0 + 2 * i + 1) * N + n0;
        float4 v0, v1;
        v0.x = lo[0] + bias[n0 + 0];
        v0.y = lo[1] + bias[n0 + 1];
        v0.z = lo[2] + bias[n0 + 2];
        v0.w = lo[3] + bias[n0 + 3];
        v1.x = hi[0] + bias[n0 + 0];
        v1.y = hi[1] + bias[n0 + 1];
        v1.z = hi[2] + bias[n0 + 2];
        v1.w = hi[3] + bias[n0 + 3];
        *reinterpret_cast<float4*>(crow0) = v0;
        *reinterpret_cast<float4*>(crow1) = v1;
    }
}

// ----------------------------- LIF scan ------------------------------------
__global__ void lif_scan_kernel(const float* __restrict__ lin_out,
                                float* __restrict__ spikes,
                                int B, int F) {
    const size_t idx = (size_t)blockIdx.x * blockDim.x + threadIdx.x;
    const size_t BF = (size_t)B * F;
    if (idx >= BF) return;

    float memb = 0.0f;
    size_t off = idx;
    #pragma unroll
    for (int t = 0; t < 16; t++) {
        memb += lin_out[off];
        float s = (memb > 1.0f) ? 1.0f : 0.0f;
        spikes[off] = s;
        memb = (s > 0.0f) ? 0.0f : memb;
        off += BF;
    }
}

// ----------------------------- launch --------------------------------------
extern "C" void kernel_launch(void* const* d_in, const int* in_sizes, int n_in,
                              void* d_out, int out_size) {
    const float* x    = (const float*)d_in[0];  // [T*B, F_IN]
    const float* w    = (const float*)d_in[1];  // [F_OUT, F_IN]
    const float* bias = (const float*)d_in[2];  // [F_OUT]

    const int F_OUT = in_sizes[2];                 // 1024
    const int F_IN  = in_sizes[1] / F_OUT;         // 1024
    const int M     = in_sizes[0] / F_IN;          // 32768
    const int T     = 16;
    const int B     = M / T;

    float* lin_out = nullptr;
    cudaGetSymbolAddress((void**)&lin_out, g_lin_out);

    dim3 grid(F_OUT / BN, M / BM);
    sgemm_bias_eigen_ffma2_kernel<<<grid, 256>>>(x, w, bias, lin_out,
                                                 M, F_OUT, F_IN);

    const size_t BF = (size_t)B * F_OUT;
    const int threads = 256;
    const int blocks = (int)((BF + threads - 1) / threads);
    lif_scan_kernel<<<blocks, threads>>>(lin_out, (float*)d_out, B, F_OUT);
}

// round 6
// speedup vs baseline: 1.2274x; 1.1285x over previous
#include <cuda_runtime.h>
#include <cuda_bf16.h>
#include <cstdint>

// ---------------------------------------------------------------------------
// SpikeLinear: out = x @ W^T + bias, then LIF scan (T=16).
//
// Round 6: same bitwise arithmetic as Round 5 (Eigen kc=248 panel replication
// via FFMA2, rel_err 0.000970705 PASS), structural overhead removal:
//   - BK=16 (64 iterations instead of 128 -> half the barriers)
//   - double-buffered shared tiles, ONE __syncthreads per iteration,
//     LDG of next tile overlapped with compute of current tile
// FFMA2 pipe floor (rt=3 due to RF banking) = ~1362 us GEMM; target <1450.
// ---------------------------------------------------------------------------

#define F_MAX   1024
#define M_MAX   32768
__device__ float g_lin_out[(size_t)M_MAX * F_MAX];   // 128 MiB scratch

#define KC 248               // Eigen panel width (validated round 4)

#define BM 128
#define BN 64
#define BK 16
#define TM 8                 // m rows per thread (4 packed pairs)
#define TN 4                 // n cols per thread

#define FMA_F32X2(d, a, b, c) \
    asm("fma.rn.f32x2 %0, %1, %2, %3;" : "=l"(d) : "l"(a), "l"(b), "l"(c))
#define ADD_F32X2_(d, a, b) \
    asm("add.rn.f32x2 %0, %1, %2;" : "=l"(d) : "l"(a), "l"(b))
#define PACK_DUP_F32(d, x) \
    asm("mov.b64 %0, {%1, %2};" : "=l"(d) : "f"(x), "f"(x))
#define UNPACK_F32X2_(lo, hi, p) \
    asm("mov.b64 {%0, %1}, %2;" : "=f"(lo), "=f"(hi) : "l"(p))

__global__ __launch_bounds__(256, 2)
void sgemm_bias_eigen_ffma2_db_kernel(const float* __restrict__ A,
                                      const float* __restrict__ W,
                                      const float* __restrict__ bias,
                                      float* __restrict__ C,
                                      int M, int N, int K) {
    __shared__ float As[2][BK][BM];   // 16 KB
    __shared__ float Ws[2][BK][BN];   // 8 KB

    const int tid  = threadIdx.x;          // 0..255
    const int brow = blockIdx.y;
    const int bcol = blockIdx.x;

    const int tcol = tid % (BN / TN);        // 0..15
    const int trow = tid / (BN / TN);        // 0..15

    // packed accumulators: [m-pair 0..3][n 0..3], each = {m_even, m_odd}
    unsigned long long cur[4][TN];
    unsigned long long tot[4][TN];
    #pragma unroll
    for (int i = 0; i < 4; i++)
        #pragma unroll
        for (int j = 0; j < TN; j++) { cur[i][j] = 0ull; tot[i][j] = 0ull; }

    const float* Ab = A + (size_t)brow * BM * K;
    const float* Wb = W + (size_t)bcol * BN * K;

    // global->shared mapping (BK=16): 128x16 A tile = 512 float4,
    // 64x16 W tile = 256 float4. 256 threads: A 2 float4, W 1 float4.
    const int ld_row = tid / 4;               // 0..63
    const int ld_col = (tid % 4) * 4;         // 0,4,8,12

    float4 rA0, rA1, rW;

    // ---- prologue: load tile 0 ----
    rA0 = *reinterpret_cast<const float4*>(Ab + (size_t)ld_row * K + ld_col);
    rA1 = *reinterpret_cast<const float4*>(Ab + (size_t)(ld_row + 64) * K + ld_col);
    rW  = *reinterpret_cast<const float4*>(Wb + (size_t)ld_row * K + ld_col);

    {   // STS into buffer 0 (transposed)
        As[0][ld_col + 0][ld_row]      = rA0.x;
        As[0][ld_col + 1][ld_row]      = rA0.y;
        As[0][ld_col + 2][ld_row]      = rA0.z;
        As[0][ld_col + 3][ld_row]      = rA0.w;
        As[0][ld_col + 0][ld_row + 64] = rA1.x;
        As[0][ld_col + 1][ld_row + 64] = rA1.y;
        As[0][ld_col + 2][ld_row + 64] = rA1.z;
        As[0][ld_col + 3][ld_row + 64] = rA1.w;
        Ws[0][ld_col + 0][ld_row]      = rW.x;
        Ws[0][ld_col + 1][ld_row]      = rW.y;
        Ws[0][ld_col + 2][ld_row]      = rW.z;
        Ws[0][ld_col + 3][ld_row]      = rW.w;
    }
    __syncthreads();

    int buf = 0;
    for (int k0 = 0; k0 < K; k0 += BK) {
        const bool has_next = (k0 + BK < K);

        // ---- LDG next tile into registers (overlaps with compute) ----
        if (has_next) {
            const float* Abn = Ab + k0 + BK;
            const float* Wbn = Wb + k0 + BK;
            rA0 = *reinterpret_cast<const float4*>(Abn + (size_t)ld_row * K + ld_col);
            rA1 = *reinterpret_cast<const float4*>(Abn + (size_t)(ld_row + 64) * K + ld_col);
            rW  = *reinterpret_cast<const float4*>(Wbn + (size_t)ld_row * K + ld_col);
        }

        // ---- fold position within this tile (at most one) ----
        // Eigen panel boundaries: k_end multiple of KC=248, or k_end == K.
        int fold_local = -1;
        {
            int next_b = ((k0 / KC) + 1) * KC;    // next 248-boundary > k0
            if (next_b <= k0 + BK)      fold_local = next_b - k0 - 1;
            else if (k0 + BK == K)      fold_local = BK - 1;
        }

        // ---- compute current buffer: strictly ascending k ----
        #pragma unroll
        for (int k = 0; k < BK; k++) {
            const ulonglong2* As2 =
                reinterpret_cast<const ulonglong2*>(&As[buf][k][trow * TM]);
            ulonglong2 al = As2[0];   // {m0m1, m2m3}
            ulonglong2 ah = As2[1];   // {m4m5, m6m7}
            unsigned long long ap[4] = {al.x, al.y, ah.x, ah.y};

            const float4* Ws4 = reinterpret_cast<const float4*>(&Ws[buf][k][0]);
            float4 w = Ws4[tcol];
            unsigned long long wp[TN];
            PACK_DUP_F32(wp[0], w.x);
            PACK_DUP_F32(wp[1], w.y);
            PACK_DUP_F32(wp[2], w.z);
            PACK_DUP_F32(wp[3], w.w);

            #pragma unroll
            for (int i = 0; i < 4; i++)
                #pragma unroll
                for (int j = 0; j < TN; j++)
                    FMA_F32X2(cur[i][j], ap[i], wp[j], cur[i][j]);

            // Eigen panel fold (bitwise-identical to rounds 4/5)
            if (k == fold_local) {
                #pragma unroll
                for (int i = 0; i < 4; i++)
                    #pragma unroll
                    for (int j = 0; j < TN; j++) {
                        ADD_F32X2_(tot[i][j], tot[i][j], cur[i][j]);
                        cur[i][j] = 0ull;
                    }
            }
        }

        // ---- STS next tile into the other buffer, single sync ----
        if (has_next) {
            const int nb = buf ^ 1;
            As[nb][ld_col + 0][ld_row]      = rA0.x;
            As[nb][ld_col + 1][ld_row]      = rA0.y;
            As[nb][ld_col + 2][ld_row]      = rA0.z;
            As[nb][ld_col + 3][ld_row]      = rA0.w;
            As[nb][ld_col + 0][ld_row + 64] = rA1.x;
            As[nb][ld_col + 1][ld_row + 64] = rA1.y;
            As[nb][ld_col + 2][ld_row + 64] = rA1.z;
            As[nb][ld_col + 3][ld_row + 64] = rA1.w;
            Ws[nb][ld_col + 0][ld_row]      = rW.x;
            Ws[nb][ld_col + 1][ld_row]      = rW.y;
            Ws[nb][ld_col + 2][ld_row]      = rW.z;
            Ws[nb][ld_col + 3][ld_row]      = rW.w;
            __syncthreads();
            buf = nb;
        }
    }

    // epilogue: unpack, scalar fp32 bias add (identical to rounds 4/5), store
    const int m0 = brow * BM + trow * TM;
    const int n0 = bcol * BN + tcol * TN;
    #pragma unroll
    for (int i = 0; i < 4; i++) {
        float lo[TN], hi[TN];
        #pragma unroll
        for (int j = 0; j < TN; j++)
            UNPACK_F32X2_(lo[j], hi[j], tot[i][j]);

        float* crow0 = C + (size_t)(m0 + 2 * i + 0) * N + n0;
        float* crow1 = C + (size_t)(m0 + 2 * i + 1) * N + n0;
        float4 v0, v1;
        v0.x = lo[0] + bias[n0 + 0];
        v0.y = lo[1] + bias[n0 + 1];
        v0.z = lo[2] + bias[n0 + 2];
        v0.w = lo[3] + bias[n0 + 3];
        v1.x = hi[0] + bias[n0 + 0];
        v1.y = hi[1] + bias[n0 + 1];
        v1.z = hi[2] + bias[n0 + 2];
        v1.w = hi[3] + bias[n0 + 3];
        *reinterpret_cast<float4*>(crow0) = v0;
        *reinterpret_cast<float4*>(crow1) = v1;
    }
}

// ----------------------------- LIF scan ------------------------------------
__global__ void lif_scan_kernel(const float* __restrict__ lin_out,
                                float* __restrict__ spikes,
                                int B, int F) {
    const size_t idx = (size_t)blockIdx.x * blockDim.x + threadIdx.x;
    const size_t BF = (size_t)B * F;
    if (idx >= BF) return;

    float memb = 0.0f;
    size_t off = idx;
    #pragma unroll
    for (int t = 0; t < 16; t++) {
        memb += lin_out[off];
        float s = (memb > 1.0f) ? 1.0f : 0.0f;
        spikes[off] = s;
        memb = (s > 0.0f) ? 0.0f : memb;
        off += BF;
    }
}

// ----------------------------- launch --------------------------------------
extern "C" void kernel_launch(void* const* d_in, const int* in_sizes, int n_in,
                              void* d_out, int out_size) {
    const float* x    = (const float*)d_in[0];  // [T*B, F_IN]
    const float* w    = (const float*)d_in[1];  // [F_OUT, F_IN]
    const float* bias = (const float*)d_in[2];  // [F_OUT]

    const int F_OUT = in_sizes[2];                 // 1024
    const int F_IN  = in_sizes[1] / F_OUT;         // 1024
    const int M     = in_sizes[0] / F_IN;          // 32768
    const int T     = 16;
    const int B     = M / T;

    float* lin_out = nullptr;
    cudaGetSymbolAddress((void**)&lin_out, g_lin_out);

    dim3 grid(F_OUT / BN, M / BM);
    sgemm_bias_eigen_ffma2_db_kernel<<<grid, 256>>>(x, w, bias, lin_out,
                                                    M, F_OUT, F_IN);

    const size_t BF = (size_t)B * F_OUT;
    const int threads = 256;
    const int blocks = (int)((BF + threads - 1) / threads);
    lif_scan_kernel<<<blocks, threads>>>(lin_out, (float*)d_out, B, F_OUT);
}

// round 7
// speedup vs baseline: 1.2530x; 1.0209x over previous
#include <cuda_runtime.h>
#include <cuda_bf16.h>
#include <cstdint>

// ---------------------------------------------------------------------------
// SpikeLinear: out = x @ W^T + bias, then LIF scan (T=16), FULLY FUSED.
//
// Round 7: fold the LIF scan into the GEMM epilogue. The M-tile is remapped
// so one block covers 8 batch rows x all 16 timesteps (tile_row =
// b_local*16 + t). Each thread then owns a half t-chain (t 0-7 or 8-15) of
// one b; the membrane potential is handed from lower to upper half via
// __shfl_up_sync(.,16) (the two halves are lanes l and l+16 of one warp).
// Eliminates the 128 MB lin_out intermediate and the separate LIF kernel.
//
// GEMM arithmetic is bitwise-identical to rounds 4-6 (Eigen kc=248 panel
// replication via FFMA2, rel_err 0.000970705): ascending-k fmaf per panel,
// ascending panel folds, + bias, then ascending-t fp32 scan.
// ---------------------------------------------------------------------------

#define KC 248               // Eigen panel width (validated round 4)

#define BM 128
#define BN 64
#define BK 16
#define TM 8                 // m rows per thread (4 packed pairs)
#define TN 4                 // n cols per thread
#define T_STEPS 16

#define FMA_F32X2(d, a, b, c) \
    asm("fma.rn.f32x2 %0, %1, %2, %3;" : "=l"(d) : "l"(a), "l"(b), "l"(c))
#define ADD_F32X2_(d, a, b) \
    asm("add.rn.f32x2 %0, %1, %2;" : "=l"(d) : "l"(a), "l"(b))
#define PACK_DUP_F32(d, x) \
    asm("mov.b64 %0, {%1, %2};" : "=l"(d) : "f"(x), "f"(x))
#define UNPACK_F32X2_(lo, hi, p) \
    asm("mov.b64 {%0, %1}, %2;" : "=f"(lo), "=f"(hi) : "l"(p))

__global__ __launch_bounds__(256, 2)
void spikelinear_fused_kernel(const float* __restrict__ A,
                              const float* __restrict__ W,
                              const float* __restrict__ bias,
                              float* __restrict__ spikes,
                              int B, int N, int K) {
    __shared__ float As[2][BK][BM];   // 16 KB
    __shared__ float Ws[2][BK][BN];   // 8 KB

    const int tid    = threadIdx.x;          // 0..255
    const int b_tile = blockIdx.y;            // batch tile (8 b's)
    const int bcol   = blockIdx.x;            // N tile

    const int tcol = tid % (BN / TN);          // 0..15
    const int trow = tid / (BN / TN);          // 0..15

    const int b_base = b_tile * (BM / T_STEPS);   // 8 b's per block

    // packed accumulators: [m-pair 0..3][n 0..3]
    unsigned long long cur[4][TN];
    unsigned long long tot[4][TN];
    #pragma unroll
    for (int i = 0; i < 4; i++)
        #pragma unroll
        for (int j = 0; j < TN; j++) { cur[i][j] = 0ull; tot[i][j] = 0ull; }

    const float* Wb = W + (size_t)bcol * BN * K;

    // loader mapping (BK=16): A tile 128x16 -> 2 float4/thread,
    // W tile 64x16 -> 1 float4/thread.
    const int ld_row = tid / 4;               // 0..63
    const int ld_col = (tid % 4) * 4;         // 0,4,8,12

    // tile_row -> global m:  b_local = tile_row>>4, t = tile_row&15,
    // m = t*B + b_base + b_local
    const int tr0 = ld_row;
    const int tr1 = ld_row + 64;
    const float* rowA0 = A + (size_t)((tr0 & 15) * B + b_base + (tr0 >> 4)) * K;
    const float* rowA1 = A + (size_t)((tr1 & 15) * B + b_base + (tr1 >> 4)) * K;
    const float* rowW  = Wb + (size_t)ld_row * K;

    float4 rA0, rA1, rW;

    // ---- prologue: load tile 0 ----
    rA0 = *reinterpret_cast<const float4*>(rowA0 + ld_col);
    rA1 = *reinterpret_cast<const float4*>(rowA1 + ld_col);
    rW  = *reinterpret_cast<const float4*>(rowW + ld_col);
    {
        As[0][ld_col + 0][tr0] = rA0.x;
        As[0][ld_col + 1][tr0] = rA0.y;
        As[0][ld_col + 2][tr0] = rA0.z;
        As[0][ld_col + 3][tr0] = rA0.w;
        As[0][ld_col + 0][tr1] = rA1.x;
        As[0][ld_col + 1][tr1] = rA1.y;
        As[0][ld_col + 2][tr1] = rA1.z;
        As[0][ld_col + 3][tr1] = rA1.w;
        Ws[0][ld_col + 0][ld_row] = rW.x;
        Ws[0][ld_col + 1][ld_row] = rW.y;
        Ws[0][ld_col + 2][ld_row] = rW.z;
        Ws[0][ld_col + 3][ld_row] = rW.w;
    }
    __syncthreads();

    int buf = 0;
    for (int k0 = 0; k0 < K; k0 += BK) {
        const bool has_next = (k0 + BK < K);

        if (has_next) {
            const int kn = k0 + BK;
            rA0 = *reinterpret_cast<const float4*>(rowA0 + kn + ld_col);
            rA1 = *reinterpret_cast<const float4*>(rowA1 + kn + ld_col);
            rW  = *reinterpret_cast<const float4*>(rowW + kn + ld_col);
        }

        // Eigen fold position within this tile (at most one)
        int fold_local = -1;
        {
            int next_b = ((k0 / KC) + 1) * KC;
            if (next_b <= k0 + BK)      fold_local = next_b - k0 - 1;
            else if (k0 + BK == K)      fold_local = BK - 1;
        }

        #pragma unroll
        for (int k = 0; k < BK; k++) {
            const ulonglong2* As2 =
                reinterpret_cast<const ulonglong2*>(&As[buf][k][trow * TM]);
            ulonglong2 al = As2[0];
            ulonglong2 ah = As2[1];
            unsigned long long ap[4] = {al.x, al.y, ah.x, ah.y};

            const float4* Ws4 = reinterpret_cast<const float4*>(&Ws[buf][k][0]);
            float4 w = Ws4[tcol];
            unsigned long long wp[TN];
            PACK_DUP_F32(wp[0], w.x);
            PACK_DUP_F32(wp[1], w.y);
            PACK_DUP_F32(wp[2], w.z);
            PACK_DUP_F32(wp[3], w.w);

            #pragma unroll
            for (int i = 0; i < 4; i++)
                #pragma unroll
                for (int j = 0; j < TN; j++)
                    FMA_F32X2(cur[i][j], ap[i], wp[j], cur[i][j]);

            if (k == fold_local) {
                #pragma unroll
                for (int i = 0; i < 4; i++)
                    #pragma unroll
                    for (int j = 0; j < TN; j++) {
                        ADD_F32X2_(tot[i][j], tot[i][j], cur[i][j]);
                        cur[i][j] = 0ull;
                    }
            }
        }

        if (has_next) {
            const int nb = buf ^ 1;
            As[nb][ld_col + 0][tr0] = rA0.x;
            As[nb][ld_col + 1][tr0] = rA0.y;
            As[nb][ld_col + 2][tr0] = rA0.z;
            As[nb][ld_col + 3][tr0] = rA0.w;
            As[nb][ld_col + 0][tr1] = rA1.x;
            As[nb][ld_col + 1][tr1] = rA1.y;
            As[nb][ld_col + 2][tr1] = rA1.z;
            As[nb][ld_col + 3][tr1] = rA1.w;
            Ws[nb][ld_col + 0][ld_row] = rW.x;
            Ws[nb][ld_col + 1][ld_row] = rW.y;
            Ws[nb][ld_col + 2][ld_row] = rW.z;
            Ws[nb][ld_col + 3][ld_row] = rW.w;
            __syncthreads();
            buf = nb;
        }
    }

    // ------------------------- fused epilogue -------------------------
    // thread rows: tile rows trow*8 + r (r=0..7)
    //   b_local = trow>>1  (fixed per thread)
    //   t       = (trow&1)*8 + r  (lower half: t 0-7, upper half: t 8-15)
    const int n0 = bcol * BN + tcol * TN;
    const int b  = b_base + (trow >> 1);
    const bool upper = (trow & 1);

    // unpack + bias (identical scalar fp32 add as rounds 4-6)
    float v[8][TN];
    #pragma unroll
    for (int i = 0; i < 4; i++) {
        float lo[TN], hi[TN];
        #pragma unroll
        for (int j = 0; j < TN; j++)
            UNPACK_F32X2_(lo[j], hi[j], tot[i][j]);
        #pragma unroll
        for (int j = 0; j < TN; j++) {
            v[2 * i + 0][j] = lo[j] + bias[n0 + j];
            v[2 * i + 1][j] = hi[j] + bias[n0 + j];
        }
    }

    // LIF scan, ascending t. Pass 1: scan from 0 (valid for lower half).
    float sp[8][TN];
    float fin[TN];
    #pragma unroll
    for (int j = 0; j < TN; j++) {
        float memb = 0.0f;
        #pragma unroll
        for (int r = 0; r < 8; r++) {
            memb += v[r][j];
            float s = (memb > 1.0f) ? 1.0f : 0.0f;
            sp[r][j] = s;
            memb = (s > 0.0f) ? 0.0f : memb;
        }
        fin[j] = memb;
    }
    // hand membrane from lower half (lane l) to upper half (lane l+16)
    #pragma unroll
    for (int j = 0; j < TN; j++)
        fin[j] = __shfl_up_sync(0xffffffffu, fin[j], 16);
    // Pass 2 for upper half: rescan with the correct initial membrane.
    if (upper) {
        #pragma unroll
        for (int j = 0; j < TN; j++) {
            float memb = fin[j];
            #pragma unroll
            for (int r = 0; r < 8; r++) {
                memb += v[r][j];
                float s = (memb > 1.0f) ? 1.0f : 0.0f;
                sp[r][j] = s;
                memb = (s > 0.0f) ? 0.0f : memb;
            }
        }
    }

    // store spikes: row m = t*B + b, t = upper*8 + r
    #pragma unroll
    for (int r = 0; r < 8; r++) {
        const int t = (upper ? 8 : 0) + r;
        float* crow = spikes + (size_t)(t * B + b) * N + n0;
        float4 o;
        o.x = sp[r][0];
        o.y = sp[r][1];
        o.z = sp[r][2];
        o.w = sp[r][3];
        *reinterpret_cast<float4*>(crow) = o;
    }
}

// ----------------------------- launch --------------------------------------
extern "C" void kernel_launch(void* const* d_in, const int* in_sizes, int n_in,
                              void* d_out, int out_size) {
    const float* x    = (const float*)d_in[0];  // [T*B, F_IN]
    const float* w    = (const float*)d_in[1];  // [F_OUT, F_IN]
    const float* bias = (const float*)d_in[2];  // [F_OUT]

    const int F_OUT = in_sizes[2];                 // 1024
    const int F_IN  = in_sizes[1] / F_OUT;         // 1024
    const int M     = in_sizes[0] / F_IN;          // 32768
    const int B     = M / T_STEPS;                 // 2048

    dim3 grid(F_OUT / BN, B / (BM / T_STEPS));     // (16, 256)
    spikelinear_fused_kernel<<<grid, 256>>>(x, w, bias, (float*)d_out,
                                            B, F_OUT, F_IN);
}